// round 5
// baseline (speedup 1.0000x reference)
#include <cuda_runtime.h>
#include <math.h>

#define BB 32
#define NN 300
#define TT 12
#define DD 64
#define MM 16
#define FF 192          // D*(HOPS+1)
#define BT (BB*TT)      // 384

// ---------------- device scratch (static: allocation-free) ----------------
__device__ float g_S [NN*NN];        // alpha1@alpha2           0.36 MB
__device__ float g_Bm[NN*NN];        // beta1@beta2             0.36 MB
__device__ float g_W [NN*DD*DD];     // trainW1@trainW2         4.9  MB
__device__ float g_A [BT*NN*NN];     // adjacency per (b,t)     138  MB
__device__ float g_G [BT*NN*DD];     // A@Hb intermediate       29.5 MB
__device__ float g_H [BT*NN*FF];     // concat [Xp|H1|H2]       88.5 MB
__device__ float g_O [BT*NN*DD];     // gcn output pre-transpose 29.5 MB

// ---------------- K0: small M=16 GEMMs ----------------
__global__ void k_small(const float* __restrict__ a1, const float* __restrict__ a2,
                        const float* __restrict__ b1, const float* __restrict__ b2,
                        const float* __restrict__ w1, const float* __restrict__ w2) {
    int idx = blockIdx.x * blockDim.x + threadIdx.x;
    int stride = gridDim.x * blockDim.x;
    for (int p = idx; p < NN*NN; p += stride) {
        int i = p / NN, j = p % NN;
        float s = 0.f, bm = 0.f;
        #pragma unroll
        for (int m = 0; m < MM; m++) {
            s  = fmaf(a1[i*MM+m], a2[m*NN+j], s);
            bm = fmaf(b1[i*MM+m], b2[m*NN+j], bm);
        }
        g_S[p] = s; g_Bm[p] = bm;
    }
    for (int p = idx; p < NN*DD*DD; p += stride) {
        int i = p / (DD*DD), c = p % (DD*DD);
        float acc = 0.f;
        #pragma unroll
        for (int m = 0; m < MM; m++) acc = fmaf(w1[i*MM+m], w2[m*DD*DD+c], acc);
        g_W[p] = acc;
    }
}

// ---------------- K1: pack X[b,d,n,t] -> g_H[bt,n,0:64] (= Xp) ----------------
__global__ void k_packX(const float* __restrict__ X) {
    int b = blockIdx.x / NN, n = blockIdx.x % NN;
    __shared__ float xs[DD][TT+1];
    const float* xp = X + (b*DD*NN + n)*TT;            // stride d: NN*TT
    for (int i = threadIdx.x; i < DD*TT; i += blockDim.x) {
        int d = i / TT, t = i % TT;
        xs[d][t] = xp[d*NN*TT + t];
    }
    __syncthreads();
    float* hp = g_H + (b*TT*NN + n)*FF;                // stride t: NN*FF
    for (int i = threadIdx.x; i < TT*DD; i += blockDim.x) {
        int t = i / DD, d = i % DD;
        hp[t*NN*FF + d] = xs[d][t];
    }
}

// ---------------- K2: adjacency A = relu(S*sin(te.adjW^T + adjB) + Bm) ----------------
// grid (BT, 5, 5), block 256, 64x64 tile, K=64, 4x4 per thread
__global__ void k_adj(const float* __restrict__ TE, const float* __restrict__ adjW,
                      const float* __restrict__ adjB) {
    int bt = blockIdx.x;
    int b = bt / TT, t = bt % TT;
    int n0 = blockIdx.y * 64;
    int k0 = blockIdx.z * 64;
    __shared__ float tes[64][DD+1];
    __shared__ float wsm[64][DD+1];

    for (int i = threadIdx.x; i < 64*16; i += 256) {
        int r = i / 16, q = i % 16;
        int n = n0 + r;
        float4 v = make_float4(0.f,0.f,0.f,0.f);
        if (n < NN) v = *(const float4*)(TE + ((b*NN + n)*TT + t)*DD + q*4);
        tes[r][q*4+0]=v.x; tes[r][q*4+1]=v.y; tes[r][q*4+2]=v.z; tes[r][q*4+3]=v.w;
    }
    for (int i = threadIdx.x; i < 64*16; i += 256) {
        int r = i / 16, q = i % 16;
        int k = k0 + r;
        float4 v = make_float4(0.f,0.f,0.f,0.f);
        if (k < NN) v = *(const float4*)(adjW + k*DD + q*4);
        wsm[r][q*4+0]=v.x; wsm[r][q*4+1]=v.y; wsm[r][q*4+2]=v.z; wsm[r][q*4+3]=v.w;
    }
    __syncthreads();

    int tx = threadIdx.x % 16, ty = threadIdx.x / 16;
    float acc[4][4] = {};
    #pragma unroll 8
    for (int d = 0; d < DD; d++) {
        float a[4], w[4];
        #pragma unroll
        for (int i = 0; i < 4; i++) a[i] = tes[ty + 16*i][d];
        #pragma unroll
        for (int j = 0; j < 4; j++) w[j] = wsm[tx + 16*j][d];
        #pragma unroll
        for (int i = 0; i < 4; i++)
            #pragma unroll
            for (int j = 0; j < 4; j++) acc[i][j] = fmaf(a[i], w[j], acc[i][j]);
    }

    float* Ap = g_A + bt*NN*NN;
    #pragma unroll
    for (int i = 0; i < 4; i++) {
        int n = n0 + ty + 16*i;
        if (n >= NN) continue;
        #pragma unroll
        for (int j = 0; j < 4; j++) {
            int k = k0 + tx + 16*j;
            if (k >= NN) continue;
            float raw = acc[i][j] + adjB[k];
            float v = __sinf(raw);
            float av = fmaf(g_S[n*NN+k], v, g_Bm[n*NN+k]);
            Ap[n*NN+k] = fmaxf(av, 0.f);
        }
    }
}

// ---------------- K3a: G[bt,n,e] = sum_k A[bt,n,k]*Hb[bt,k,e], K=300 ----------------
// grid (BT, 5), block 256, 64(n) x 64(e) tile
__global__ void k_hop_agg(int hb_off) {
    int bt = blockIdx.x;
    int n0 = blockIdx.y * 64;
    __shared__ float As[64][65];
    __shared__ float Hs[64][DD];
    int tx = threadIdx.x % 16, ty = threadIdx.x / 16;
    float acc[4][4] = {};
    const float* Ap = g_A + bt*NN*NN;
    const float* Hp = g_H + bt*NN*FF + hb_off;

    for (int k0 = 0; k0 < NN; k0 += 64) {
        for (int i = threadIdx.x; i < 64*64; i += 256) {
            int r = i / 64, kk = i % 64;
            int n = n0 + r, k = k0 + kk;
            As[r][kk] = (n < NN && k < NN) ? Ap[n*NN + k] : 0.f;
        }
        for (int i = threadIdx.x; i < 64*16; i += 256) {
            int kk = i / 16, q = i % 16;
            int k = k0 + kk;
            float4 v = make_float4(0.f,0.f,0.f,0.f);
            if (k < NN) v = *(const float4*)(Hp + k*FF + q*4);
            *(float4*)&Hs[kk][q*4] = v;
        }
        __syncthreads();
        #pragma unroll 8
        for (int kk = 0; kk < 64; kk++) {
            float a[4], h[4];
            #pragma unroll
            for (int i = 0; i < 4; i++) a[i] = As[ty + 16*i][kk];
            #pragma unroll
            for (int j = 0; j < 4; j++) h[j] = Hs[kk][tx + 16*j];
            #pragma unroll
            for (int i = 0; i < 4; i++)
                #pragma unroll
                for (int j = 0; j < 4; j++) acc[i][j] = fmaf(a[i], h[j], acc[i][j]);
        }
        __syncthreads();
    }

    float* Gp = g_G + bt*NN*DD;
    #pragma unroll
    for (int i = 0; i < 4; i++) {
        int n = n0 + ty + 16*i;
        if (n >= NN) continue;
        #pragma unroll
        for (int j = 0; j < 4; j++) Gp[n*DD + tx + 16*j] = acc[i][j];
    }
}

// ---------------- K3b: per-node H2[bt,n,d] = gate(Xp + G[bt,n,:]@W[n]) ----------------
// grid (NN, BT/64), block 256, 64(bt) x 64(d) tile, K=64; W[n] cached in smem
__global__ void k_hop_node(int hout_off) {
    int n  = blockIdx.x;
    int r0 = blockIdx.y * 64;       // bt base
    __shared__ float Gsm[64][65];   // [bt_local][e]
    __shared__ float Wsm[64][DD];   // [e][d]
    int tx = threadIdx.x % 16, ty = threadIdx.x / 16;

    for (int i = threadIdx.x; i < 64*16; i += 256) {
        int r = i / 16, q = i % 16;
        float4 v = *(const float4*)(g_G + ((r0 + r)*NN + n)*DD + q*4);
        Gsm[r][q*4+0]=v.x; Gsm[r][q*4+1]=v.y; Gsm[r][q*4+2]=v.z; Gsm[r][q*4+3]=v.w;
    }
    for (int i = threadIdx.x; i < 64*16; i += 256) {
        int e = i / 16, q = i % 16;
        float4 v = *(const float4*)(g_W + (n*DD + e)*DD + q*4);
        *(float4*)&Wsm[e][q*4] = v;
    }
    __syncthreads();

    float acc[4][4] = {};
    #pragma unroll 8
    for (int e = 0; e < DD; e++) {
        float gv[4], wv[4];
        #pragma unroll
        for (int i = 0; i < 4; i++) gv[i] = Gsm[ty + 16*i][e];
        #pragma unroll
        for (int j = 0; j < 4; j++) wv[j] = Wsm[e][tx + 16*j];
        #pragma unroll
        for (int i = 0; i < 4; i++)
            #pragma unroll
            for (int j = 0; j < 4; j++) acc[i][j] = fmaf(gv[i], wv[j], acc[i][j]);
    }

    #pragma unroll
    for (int i = 0; i < 4; i++) {
        int r = r0 + ty + 16*i;                       // bt
        const float* xrow = g_H + (r*NN + n)*FF;      // slice 0 = Xp
        float*       orow = g_H + (r*NN + n)*FF + hout_off;
        #pragma unroll
        for (int j = 0; j < 4; j++) {
            int d = tx + 16*j;
            float pre = xrow[d] + acc[i][j];
            float sg  = 1.f / (1.f + expf(-pre));
            orow[d] = sg * tanhf(pre);
        }
    }
}

// ---------------- K4: Hout[r,d] = H[r,:]@gcnW[d,:]^T + gcnB, r = bt*NN+n ----------------
// grid (BT*NN/64), block 256, 64x64 tile, K=192
__global__ void k_gcn(const float* __restrict__ gcnW, const float* __restrict__ gcnB) {
    int r0 = blockIdx.x * 64;
    __shared__ float Hsm[64][65];   // [r_local][kk]
    __shared__ float Wsm[64][65];   // [kk][d]  (gcnW transposed)
    int tx = threadIdx.x % 16, ty = threadIdx.x / 16;
    float acc[4][4] = {};

    for (int f0 = 0; f0 < FF; f0 += 64) {
        for (int i = threadIdx.x; i < 64*16; i += 256) {
            int r = i / 16, q = i % 16;
            float4 v = *(const float4*)(g_H + (r0 + r)*FF + f0 + q*4);
            Hsm[r][q*4+0]=v.x; Hsm[r][q*4+1]=v.y; Hsm[r][q*4+2]=v.z; Hsm[r][q*4+3]=v.w;
        }
        for (int i = threadIdx.x; i < 64*16; i += 256) {
            int d = i / 16, q = i % 16;
            float4 v = *(const float4*)(gcnW + d*FF + f0 + q*4);
            Wsm[q*4+0][d]=v.x; Wsm[q*4+1][d]=v.y; Wsm[q*4+2][d]=v.z; Wsm[q*4+3][d]=v.w;
        }
        __syncthreads();
        #pragma unroll 8
        for (int kk = 0; kk < 64; kk++) {
            float hv[4], wv[4];
            #pragma unroll
            for (int i = 0; i < 4; i++) hv[i] = Hsm[ty + 16*i][kk];
            #pragma unroll
            for (int j = 0; j < 4; j++) wv[j] = Wsm[kk][tx + 16*j];
            #pragma unroll
            for (int i = 0; i < 4; i++)
                #pragma unroll
                for (int j = 0; j < 4; j++) acc[i][j] = fmaf(hv[i], wv[j], acc[i][j]);
        }
        __syncthreads();
    }

    #pragma unroll
    for (int i = 0; i < 4; i++) {
        int r = r0 + ty + 16*i;
        #pragma unroll
        for (int j = 0; j < 4; j++) {
            int d = tx + 16*j;
            g_O[r*DD + d] = acc[i][j] + gcnB[d];
        }
    }
}

// ---------------- K5: out[b,d,n,t] = g_O[bt,n,d] ----------------
__global__ void k_out(float* __restrict__ out) {
    int b = blockIdx.x / NN, n = blockIdx.x % NN;
    __shared__ float ts[TT][DD+1];
    for (int i = threadIdx.x; i < TT*DD; i += blockDim.x) {
        int t = i / DD, d = i % DD;
        ts[t][d] = g_O[((b*TT + t)*NN + n)*DD + d];
    }
    __syncthreads();
    float* op = out + (b*DD*NN + n)*TT;
    for (int i = threadIdx.x; i < DD*TT; i += blockDim.x) {
        int d = i / TT, t = i % TT;
        op[d*NN*TT + t] = ts[t][d];
    }
}

// ---------------- launch ----------------
extern "C" void kernel_launch(void* const* d_in, const int* in_sizes, int n_in,
                              void* d_out, int out_size) {
    const float* X    = (const float*)d_in[0];
    const float* TE   = (const float*)d_in[1];
    const float* adjW = (const float*)d_in[2];
    const float* adjB = (const float*)d_in[3];
    const float* w1   = (const float*)d_in[4];
    const float* w2   = (const float*)d_in[5];
    const float* a1   = (const float*)d_in[6];
    const float* a2   = (const float*)d_in[7];
    const float* b1   = (const float*)d_in[8];
    const float* b2   = (const float*)d_in[9];
    const float* gw   = (const float*)d_in[10];
    const float* gb   = (const float*)d_in[11];
    float* out = (float*)d_out;

    k_small<<<352, 256>>>(a1, a2, b1, b2, w1, w2);
    k_packX<<<BB*NN, 128>>>(X);
    k_adj<<<dim3(BT, 5, 5), 256>>>(TE, adjW, adjB);
    for (int hop = 1; hop <= 2; hop++) {
        k_hop_agg <<<dim3(BT, 5), 256>>>((hop - 1) * DD);
        k_hop_node<<<dim3(NN, BT/64), 256>>>(hop * DD);
    }
    k_gcn<<<BT*NN/64, 256>>>(gw, gb);
    k_out<<<BB*NN, 128>>>(out);
}

// round 8
// speedup vs baseline: 1.0071x; 1.0071x over previous
#include <cuda_runtime.h>
#include <math.h>

#define BB 32
#define NN 300
#define TT 12
#define DD 64
#define MM 16
#define FF 192          // D*(HOPS+1)
#define BT (BB*TT)      // 384

// ---------------- device scratch (static: allocation-free) ----------------
__device__ float g_S [NN*NN];        // alpha1@alpha2           0.36 MB
__device__ float g_Bm[NN*NN];        // beta1@beta2             0.36 MB
__device__ float g_W [NN*DD*DD];     // trainW1@trainW2         4.9  MB
__device__ float g_A [BT*NN*NN];     // adjacency per (b,t)     138  MB
__device__ float g_G [BT*NN*DD];     // A@Hb intermediate       29.5 MB
__device__ float g_H [BT*NN*FF];     // concat [Xp|H1|H2]       88.5 MB
__device__ float g_O [BT*NN*DD];     // gcn output pre-transpose 29.5 MB

// ---------------- K0: small M=16 GEMMs ----------------
__global__ void k_small(const float* __restrict__ a1, const float* __restrict__ a2,
                        const float* __restrict__ b1, const float* __restrict__ b2,
                        const float* __restrict__ w1, const float* __restrict__ w2) {
    int idx = blockIdx.x * blockDim.x + threadIdx.x;
    int stride = gridDim.x * blockDim.x;
    for (int p = idx; p < NN*NN; p += stride) {
        int i = p / NN, j = p % NN;
        float s = 0.f, bm = 0.f;
        #pragma unroll
        for (int m = 0; m < MM; m++) {
            s  = fmaf(a1[i*MM+m], a2[m*NN+j], s);
            bm = fmaf(b1[i*MM+m], b2[m*NN+j], bm);
        }
        g_S[p] = s; g_Bm[p] = bm;
    }
    for (int p = idx; p < NN*DD*DD; p += stride) {
        int i = p / (DD*DD), c = p % (DD*DD);
        float acc = 0.f;
        #pragma unroll
        for (int m = 0; m < MM; m++) acc = fmaf(w1[i*MM+m], w2[m*DD*DD+c], acc);
        g_W[p] = acc;
    }
}

// ---------------- K1: pack X[b,d,n,t] -> g_H[bt,n,0:64] (= Xp) ----------------
__global__ void k_packX(const float* __restrict__ X) {
    int b = blockIdx.x / NN, n = blockIdx.x % NN;
    __shared__ float xs[DD][TT+1];
    const float* xp = X + (b*DD*NN + n)*TT;            // stride d: NN*TT
    for (int i = threadIdx.x; i < DD*TT; i += blockDim.x) {
        int d = i / TT, t = i % TT;
        xs[d][t] = xp[d*NN*TT + t];
    }
    __syncthreads();
    float* hp = g_H + (b*TT*NN + n)*FF;                // stride t: NN*FF
    for (int i = threadIdx.x; i < TT*DD; i += blockDim.x) {
        int t = i / DD, d = i % DD;
        hp[t*NN*FF + d] = xs[d][t];
    }
}

// ---------------- K2: adjacency A = relu(S*sin(te.adjW^T + adjB) + Bm) ----------------
// grid (BT, 5, 5), block 256, 64x64 tile, K=64, 4x4 per thread
__global__ void k_adj(const float* __restrict__ TE, const float* __restrict__ adjW,
                      const float* __restrict__ adjB) {
    int bt = blockIdx.x;
    int b = bt / TT, t = bt % TT;
    int n0 = blockIdx.y * 64;
    int k0 = blockIdx.z * 64;
    __shared__ float tes[64][DD+1];
    __shared__ float wsm[64][DD+1];

    for (int i = threadIdx.x; i < 64*16; i += 256) {
        int r = i / 16, q = i % 16;
        int n = n0 + r;
        float4 v = make_float4(0.f,0.f,0.f,0.f);
        if (n < NN) v = *(const float4*)(TE + ((b*NN + n)*TT + t)*DD + q*4);
        tes[r][q*4+0]=v.x; tes[r][q*4+1]=v.y; tes[r][q*4+2]=v.z; tes[r][q*4+3]=v.w;
    }
    for (int i = threadIdx.x; i < 64*16; i += 256) {
        int r = i / 16, q = i % 16;
        int k = k0 + r;
        float4 v = make_float4(0.f,0.f,0.f,0.f);
        if (k < NN) v = *(const float4*)(adjW + k*DD + q*4);
        wsm[r][q*4+0]=v.x; wsm[r][q*4+1]=v.y; wsm[r][q*4+2]=v.z; wsm[r][q*4+3]=v.w;
    }
    __syncthreads();

    int tx = threadIdx.x % 16, ty = threadIdx.x / 16;
    float acc[4][4] = {};
    #pragma unroll 8
    for (int d = 0; d < DD; d++) {
        float a[4], w[4];
        #pragma unroll
        for (int i = 0; i < 4; i++) a[i] = tes[ty + 16*i][d];
        #pragma unroll
        for (int j = 0; j < 4; j++) w[j] = wsm[tx + 16*j][d];
        #pragma unroll
        for (int i = 0; i < 4; i++)
            #pragma unroll
            for (int j = 0; j < 4; j++) acc[i][j] = fmaf(a[i], w[j], acc[i][j]);
    }

    float* Ap = g_A + bt*NN*NN;
    #pragma unroll
    for (int i = 0; i < 4; i++) {
        int n = n0 + ty + 16*i;
        if (n >= NN) continue;
        #pragma unroll
        for (int j = 0; j < 4; j++) {
            int k = k0 + tx + 16*j;
            if (k >= NN) continue;
            float raw = acc[i][j] + adjB[k];
            float v = __sinf(raw);
            float av = fmaf(g_S[n*NN+k], v, g_Bm[n*NN+k]);
            Ap[n*NN+k] = fmaxf(av, 0.f);
        }
    }
}

// ---------------- K3a: G[bt,n,e] = sum_k A[bt,n,k]*Hb[bt,k,e], K=300 ----------------
// grid (BT, 5), block 256, 64(n) x 64(e) tile
__global__ void k_hop_agg(int hb_off) {
    int bt = blockIdx.x;
    int n0 = blockIdx.y * 64;
    __shared__ float As[64][65];
    __shared__ float Hs[64][DD];
    int tx = threadIdx.x % 16, ty = threadIdx.x / 16;
    float acc[4][4] = {};
    const float* Ap = g_A + bt*NN*NN;
    const float* Hp = g_H + bt*NN*FF + hb_off;

    for (int k0 = 0; k0 < NN; k0 += 64) {
        for (int i = threadIdx.x; i < 64*64; i += 256) {
            int r = i / 64, kk = i % 64;
            int n = n0 + r, k = k0 + kk;
            As[r][kk] = (n < NN && k < NN) ? Ap[n*NN + k] : 0.f;
        }
        for (int i = threadIdx.x; i < 64*16; i += 256) {
            int kk = i / 16, q = i % 16;
            int k = k0 + kk;
            float4 v = make_float4(0.f,0.f,0.f,0.f);
            if (k < NN) v = *(const float4*)(Hp + k*FF + q*4);
            *(float4*)&Hs[kk][q*4] = v;
        }
        __syncthreads();
        #pragma unroll 8
        for (int kk = 0; kk < 64; kk++) {
            float a[4], h[4];
            #pragma unroll
            for (int i = 0; i < 4; i++) a[i] = As[ty + 16*i][kk];
            #pragma unroll
            for (int j = 0; j < 4; j++) h[j] = Hs[kk][tx + 16*j];
            #pragma unroll
            for (int i = 0; i < 4; i++)
                #pragma unroll
                for (int j = 0; j < 4; j++) acc[i][j] = fmaf(a[i], h[j], acc[i][j]);
        }
        __syncthreads();
    }

    float* Gp = g_G + bt*NN*DD;
    #pragma unroll
    for (int i = 0; i < 4; i++) {
        int n = n0 + ty + 16*i;
        if (n >= NN) continue;
        #pragma unroll
        for (int j = 0; j < 4; j++) Gp[n*DD + tx + 16*j] = acc[i][j];
    }
}

// ---------------- K3b: per-node H2[bt,n,d] = gate(Xp + G[bt,n,:]@W[n]) ----------------
// grid (NN, BT/64), block 256, 64(bt) x 64(d) tile, K=64; W[n] cached in smem
__global__ void k_hop_node(int hout_off) {
    int n  = blockIdx.x;
    int r0 = blockIdx.y * 64;       // bt base
    __shared__ float Gsm[64][65];   // [bt_local][e]
    __shared__ float Wsm[64][DD];   // [e][d]
    int tx = threadIdx.x % 16, ty = threadIdx.x / 16;

    for (int i = threadIdx.x; i < 64*16; i += 256) {
        int r = i / 16, q = i % 16;
        float4 v = *(const float4*)(g_G + ((r0 + r)*NN + n)*DD + q*4);
        Gsm[r][q*4+0]=v.x; Gsm[r][q*4+1]=v.y; Gsm[r][q*4+2]=v.z; Gsm[r][q*4+3]=v.w;
    }
    for (int i = threadIdx.x; i < 64*16; i += 256) {
        int e = i / 16, q = i % 16;
        float4 v = *(const float4*)(g_W + (n*DD + e)*DD + q*4);
        *(float4*)&Wsm[e][q*4] = v;
    }
    __syncthreads();

    float acc[4][4] = {};
    #pragma unroll 8
    for (int e = 0; e < DD; e++) {
        float gv[4], wv[4];
        #pragma unroll
        for (int i = 0; i < 4; i++) gv[i] = Gsm[ty + 16*i][e];
        #pragma unroll
        for (int j = 0; j < 4; j++) wv[j] = Wsm[e][tx + 16*j];
        #pragma unroll
        for (int i = 0; i < 4; i++)
            #pragma unroll
            for (int j = 0; j < 4; j++) acc[i][j] = fmaf(gv[i], wv[j], acc[i][j]);
    }

    #pragma unroll
    for (int i = 0; i < 4; i++) {
        int r = r0 + ty + 16*i;                       // bt
        const float* xrow = g_H + (r*NN + n)*FF;      // slice 0 = Xp
        float*       orow = g_H + (r*NN + n)*FF + hout_off;
        #pragma unroll
        for (int j = 0; j < 4; j++) {
            int d = tx + 16*j;
            float pre = xrow[d] + acc[i][j];
            float sg  = 1.f / (1.f + expf(-pre));
            orow[d] = sg * tanhf(pre);
        }
    }
}

// ---------------- K4: Hout[r,d] = H[r,:]@gcnW[d,:]^T + gcnB, r = bt*NN+n ----------------
// grid (BT*NN/64), block 256, 64x64 tile, K=192
__global__ void k_gcn(const float* __restrict__ gcnW, const float* __restrict__ gcnB) {
    int r0 = blockIdx.x * 64;
    __shared__ float Hsm[64][65];   // [r_local][kk]
    __shared__ float Wsm[64][65];   // [kk][d]  (gcnW transposed)
    int tx = threadIdx.x % 16, ty = threadIdx.x / 16;
    float acc[4][4] = {};

    for (int f0 = 0; f0 < FF; f0 += 64) {
        for (int i = threadIdx.x; i < 64*16; i += 256) {
            int r = i / 16, q = i % 16;
            float4 v = *(const float4*)(g_H + (r0 + r)*FF + f0 + q*4);
            Hsm[r][q*4+0]=v.x; Hsm[r][q*4+1]=v.y; Hsm[r][q*4+2]=v.z; Hsm[r][q*4+3]=v.w;
        }
        for (int i = threadIdx.x; i < 64*16; i += 256) {
            int d = i / 16, q = i % 16;
            float4 v = *(const float4*)(gcnW + d*FF + f0 + q*4);
            Wsm[q*4+0][d]=v.x; Wsm[q*4+1][d]=v.y; Wsm[q*4+2][d]=v.z; Wsm[q*4+3][d]=v.w;
        }
        __syncthreads();
        #pragma unroll 8
        for (int kk = 0; kk < 64; kk++) {
            float hv[4], wv[4];
            #pragma unroll
            for (int i = 0; i < 4; i++) hv[i] = Hsm[ty + 16*i][kk];
            #pragma unroll
            for (int j = 0; j < 4; j++) wv[j] = Wsm[kk][tx + 16*j];
            #pragma unroll
            for (int i = 0; i < 4; i++)
                #pragma unroll
                for (int j = 0; j < 4; j++) acc[i][j] = fmaf(hv[i], wv[j], acc[i][j]);
        }
        __syncthreads();
    }

    #pragma unroll
    for (int i = 0; i < 4; i++) {
        int r = r0 + ty + 16*i;
        #pragma unroll
        for (int j = 0; j < 4; j++) {
            int d = tx + 16*j;
            g_O[r*DD + d] = acc[i][j] + gcnB[d];
        }
    }
}

// ---------------- K5: out[b,d,n,t] = g_O[bt,n,d] ----------------
__global__ void k_out(float* __restrict__ out) {
    int b = blockIdx.x / NN, n = blockIdx.x % NN;
    __shared__ float ts[TT][DD+1];
    for (int i = threadIdx.x; i < TT*DD; i += blockDim.x) {
        int t = i / DD, d = i % DD;
        ts[t][d] = g_O[((b*TT + t)*NN + n)*DD + d];
    }
    __syncthreads();
    float* op = out + (b*DD*NN + n)*TT;
    for (int i = threadIdx.x; i < DD*TT; i += blockDim.x) {
        int d = i / TT, t = i % TT;
        op[d*NN*TT + t] = ts[t][d];
    }
}

// ---------------- launch ----------------
extern "C" void kernel_launch(void* const* d_in, const int* in_sizes, int n_in,
                              void* d_out, int out_size) {
    const float* X    = (const float*)d_in[0];
    const float* TE   = (const float*)d_in[1];
    const float* adjW = (const float*)d_in[2];
    const float* adjB = (const float*)d_in[3];
    const float* w1   = (const float*)d_in[4];
    const float* w2   = (const float*)d_in[5];
    const float* a1   = (const float*)d_in[6];
    const float* a2   = (const float*)d_in[7];
    const float* b1   = (const float*)d_in[8];
    const float* b2   = (const float*)d_in[9];
    const float* gw   = (const float*)d_in[10];
    const float* gb   = (const float*)d_in[11];
    float* out = (float*)d_out;

    k_small<<<352, 256>>>(a1, a2, b1, b2, w1, w2);
    k_packX<<<BB*NN, 128>>>(X);
    k_adj<<<dim3(BT, 5, 5), 256>>>(TE, adjW, adjB);
    for (int hop = 1; hop <= 2; hop++) {
        k_hop_agg <<<dim3(BT, 5), 256>>>((hop - 1) * DD);
        k_hop_node<<<dim3(NN, BT/64), 256>>>(hop * DD);
    }
    k_gcn<<<BT*NN/64, 256>>>(gw, gb);
    k_out<<<BB*NN, 128>>>(out);
}

// round 9
// speedup vs baseline: 1.0094x; 1.0023x over previous
#include <cuda_runtime.h>
#include <math.h>

#define BB 32
#define NN 300
#define TT 12
#define DD 64
#define MM 16
#define FF 192          // D*(HOPS+1)
#define BT (BB*TT)      // 384

// ---------------- device scratch (static: allocation-free) ----------------
__device__ float g_S [NN*NN];        // alpha1@alpha2           0.36 MB
__device__ float g_Bm[NN*NN];        // beta1@beta2             0.36 MB
__device__ float g_W [NN*DD*DD];     // trainW1@trainW2         4.9  MB
__device__ float g_A [BT*NN*NN];     // adjacency per (b,t)     138  MB
__device__ float g_G [BT*NN*DD];     // A@Hb intermediate       29.5 MB
__device__ float g_H [BT*NN*FF];     // concat [Xp|H1|H2]       88.5 MB
__device__ float g_O [BT*NN*DD];     // gcn output pre-transpose 29.5 MB

// ---------------- K0: small M=16 GEMMs ----------------
__global__ void k_small(const float* __restrict__ a1, const float* __restrict__ a2,
                        const float* __restrict__ b1, const float* __restrict__ b2,
                        const float* __restrict__ w1, const float* __restrict__ w2) {
    int idx = blockIdx.x * blockDim.x + threadIdx.x;
    int stride = gridDim.x * blockDim.x;
    for (int p = idx; p < NN*NN; p += stride) {
        int i = p / NN, j = p % NN;
        float s = 0.f, bm = 0.f;
        #pragma unroll
        for (int m = 0; m < MM; m++) {
            s  = fmaf(a1[i*MM+m], a2[m*NN+j], s);
            bm = fmaf(b1[i*MM+m], b2[m*NN+j], bm);
        }
        g_S[p] = s; g_Bm[p] = bm;
    }
    for (int p = idx; p < NN*DD*DD; p += stride) {
        int i = p / (DD*DD), c = p % (DD*DD);
        float acc = 0.f;
        #pragma unroll
        for (int m = 0; m < MM; m++) acc = fmaf(w1[i*MM+m], w2[m*DD*DD+c], acc);
        g_W[p] = acc;
    }
}

// ---------------- K1: pack X[b,d,n,t] -> g_H[bt,n,0:64] (= Xp) ----------------
__global__ void k_packX(const float* __restrict__ X) {
    int b = blockIdx.x / NN, n = blockIdx.x % NN;
    __shared__ float xs[DD][TT+1];
    const float* xp = X + (b*DD*NN + n)*TT;            // stride d: NN*TT
    for (int i = threadIdx.x; i < DD*TT; i += blockDim.x) {
        int d = i / TT, t = i % TT;
        xs[d][t] = xp[d*NN*TT + t];
    }
    __syncthreads();
    float* hp = g_H + (b*TT*NN + n)*FF;                // stride t: NN*FF
    for (int i = threadIdx.x; i < TT*DD; i += blockDim.x) {
        int t = i / DD, d = i % DD;
        hp[t*NN*FF + d] = xs[d][t];
    }
}

// ---------------- K2: adjacency A = relu(S*sin(te.adjW^T + adjB) + Bm) ----------------
// grid (BT, 5, 5), block 256, 64x64 tile, K=64, 4x4 per thread
__global__ void k_adj(const float* __restrict__ TE, const float* __restrict__ adjW,
                      const float* __restrict__ adjB) {
    int bt = blockIdx.x;
    int b = bt / TT, t = bt % TT;
    int n0 = blockIdx.y * 64;
    int k0 = blockIdx.z * 64;
    __shared__ float tes[64][DD+1];
    __shared__ float wsm[64][DD+1];

    for (int i = threadIdx.x; i < 64*16; i += 256) {
        int r = i / 16, q = i % 16;
        int n = n0 + r;
        float4 v = make_float4(0.f,0.f,0.f,0.f);
        if (n < NN) v = *(const float4*)(TE + ((b*NN + n)*TT + t)*DD + q*4);
        tes[r][q*4+0]=v.x; tes[r][q*4+1]=v.y; tes[r][q*4+2]=v.z; tes[r][q*4+3]=v.w;
    }
    for (int i = threadIdx.x; i < 64*16; i += 256) {
        int r = i / 16, q = i % 16;
        int k = k0 + r;
        float4 v = make_float4(0.f,0.f,0.f,0.f);
        if (k < NN) v = *(const float4*)(adjW + k*DD + q*4);
        wsm[r][q*4+0]=v.x; wsm[r][q*4+1]=v.y; wsm[r][q*4+2]=v.z; wsm[r][q*4+3]=v.w;
    }
    __syncthreads();

    int tx = threadIdx.x % 16, ty = threadIdx.x / 16;
    float acc[4][4] = {};
    #pragma unroll 8
    for (int d = 0; d < DD; d++) {
        float a[4], w[4];
        #pragma unroll
        for (int i = 0; i < 4; i++) a[i] = tes[ty + 16*i][d];
        #pragma unroll
        for (int j = 0; j < 4; j++) w[j] = wsm[tx + 16*j][d];
        #pragma unroll
        for (int i = 0; i < 4; i++)
            #pragma unroll
            for (int j = 0; j < 4; j++) acc[i][j] = fmaf(a[i], w[j], acc[i][j]);
    }

    float* Ap = g_A + bt*NN*NN;
    #pragma unroll
    for (int i = 0; i < 4; i++) {
        int n = n0 + ty + 16*i;
        if (n >= NN) continue;
        #pragma unroll
        for (int j = 0; j < 4; j++) {
            int k = k0 + tx + 16*j;
            if (k >= NN) continue;
            float raw = acc[i][j] + adjB[k];
            float v = __sinf(raw);
            float av = fmaf(g_S[n*NN+k], v, g_Bm[n*NN+k]);
            Ap[n*NN+k] = fmaxf(av, 0.f);
        }
    }
}

// ---------------- K3a: G[bt,n,e] = sum_k A[bt,n,k]*Hb[bt,k,e], K=300 ----------------
// grid (BT, 5), block 256, 64(n) x 64(e) tile
__global__ void k_hop_agg(int hb_off) {
    int bt = blockIdx.x;
    int n0 = blockIdx.y * 64;
    __shared__ float As[64][65];
    __shared__ float Hs[64][DD];
    int tx = threadIdx.x % 16, ty = threadIdx.x / 16;
    float acc[4][4] = {};
    const float* Ap = g_A + bt*NN*NN;
    const float* Hp = g_H + bt*NN*FF + hb_off;

    for (int k0 = 0; k0 < NN; k0 += 64) {
        for (int i = threadIdx.x; i < 64*64; i += 256) {
            int r = i / 64, kk = i % 64;
            int n = n0 + r, k = k0 + kk;
            As[r][kk] = (n < NN && k < NN) ? Ap[n*NN + k] : 0.f;
        }
        for (int i = threadIdx.x; i < 64*16; i += 256) {
            int kk = i / 16, q = i % 16;
            int k = k0 + kk;
            float4 v = make_float4(0.f,0.f,0.f,0.f);
            if (k < NN) v = *(const float4*)(Hp + k*FF + q*4);
            *(float4*)&Hs[kk][q*4] = v;
        }
        __syncthreads();
        #pragma unroll 8
        for (int kk = 0; kk < 64; kk++) {
            float a[4], h[4];
            #pragma unroll
            for (int i = 0; i < 4; i++) a[i] = As[ty + 16*i][kk];
            #pragma unroll
            for (int j = 0; j < 4; j++) h[j] = Hs[kk][tx + 16*j];
            #pragma unroll
            for (int i = 0; i < 4; i++)
                #pragma unroll
                for (int j = 0; j < 4; j++) acc[i][j] = fmaf(a[i], h[j], acc[i][j]);
        }
        __syncthreads();
    }

    float* Gp = g_G + bt*NN*DD;
    #pragma unroll
    for (int i = 0; i < 4; i++) {
        int n = n0 + ty + 16*i;
        if (n >= NN) continue;
        #pragma unroll
        for (int j = 0; j < 4; j++) Gp[n*DD + tx + 16*j] = acc[i][j];
    }
}

// ---------------- K3b: per-node H2[bt,n,d] = gate(Xp + G[bt,n,:]@W[n]) ----------------
// grid (NN, BT/64), block 256, 64(bt) x 64(d) tile, K=64; W[n] cached in smem
__global__ void k_hop_node(int hout_off) {
    int n  = blockIdx.x;
    int r0 = blockIdx.y * 64;       // bt base
    __shared__ float Gsm[64][65];   // [bt_local][e]
    __shared__ float Wsm[64][DD];   // [e][d]
    int tx = threadIdx.x % 16, ty = threadIdx.x / 16;

    for (int i = threadIdx.x; i < 64*16; i += 256) {
        int r = i / 16, q = i % 16;
        float4 v = *(const float4*)(g_G + ((r0 + r)*NN + n)*DD + q*4);
        Gsm[r][q*4+0]=v.x; Gsm[r][q*4+1]=v.y; Gsm[r][q*4+2]=v.z; Gsm[r][q*4+3]=v.w;
    }
    for (int i = threadIdx.x; i < 64*16; i += 256) {
        int e = i / 16, q = i % 16;
        float4 v = *(const float4*)(g_W + (n*DD + e)*DD + q*4);
        *(float4*)&Wsm[e][q*4] = v;
    }
    __syncthreads();

    float acc[4][4] = {};
    #pragma unroll 8
    for (int e = 0; e < DD; e++) {
        float gv[4], wv[4];
        #pragma unroll
        for (int i = 0; i < 4; i++) gv[i] = Gsm[ty + 16*i][e];
        #pragma unroll
        for (int j = 0; j < 4; j++) wv[j] = Wsm[e][tx + 16*j];
        #pragma unroll
        for (int i = 0; i < 4; i++)
            #pragma unroll
            for (int j = 0; j < 4; j++) acc[i][j] = fmaf(gv[i], wv[j], acc[i][j]);
    }

    #pragma unroll
    for (int i = 0; i < 4; i++) {
        int r = r0 + ty + 16*i;                       // bt
        const float* xrow = g_H + (r*NN + n)*FF;      // slice 0 = Xp
        float*       orow = g_H + (r*NN + n)*FF + hout_off;
        #pragma unroll
        for (int j = 0; j < 4; j++) {
            int d = tx + 16*j;
            float pre = xrow[d] + acc[i][j];
            float sg  = 1.f / (1.f + expf(-pre));
            orow[d] = sg * tanhf(pre);
        }
    }
}

// ---------------- K4: Hout[r,d] = H[r,:]@gcnW[d,:]^T + gcnB, r = bt*NN+n ----------------
// grid (BT*NN/64), block 256, 64x64 tile, K=192
__global__ void k_gcn(const float* __restrict__ gcnW, const float* __restrict__ gcnB) {
    int r0 = blockIdx.x * 64;
    __shared__ float Hsm[64][65];   // [r_local][kk]
    __shared__ float Wsm[64][65];   // [kk][d]  (gcnW transposed)
    int tx = threadIdx.x % 16, ty = threadIdx.x / 16;
    float acc[4][4] = {};

    for (int f0 = 0; f0 < FF; f0 += 64) {
        for (int i = threadIdx.x; i < 64*16; i += 256) {
            int r = i / 16, q = i % 16;
            float4 v = *(const float4*)(g_H + (r0 + r)*FF + f0 + q*4);
            Hsm[r][q*4+0]=v.x; Hsm[r][q*4+1]=v.y; Hsm[r][q*4+2]=v.z; Hsm[r][q*4+3]=v.w;
        }
        for (int i = threadIdx.x; i < 64*16; i += 256) {
            int d = i / 16, q = i % 16;
            float4 v = *(const float4*)(gcnW + d*FF + f0 + q*4);
            Wsm[q*4+0][d]=v.x; Wsm[q*4+1][d]=v.y; Wsm[q*4+2][d]=v.z; Wsm[q*4+3][d]=v.w;
        }
        __syncthreads();
        #pragma unroll 8
        for (int kk = 0; kk < 64; kk++) {
            float hv[4], wv[4];
            #pragma unroll
            for (int i = 0; i < 4; i++) hv[i] = Hsm[ty + 16*i][kk];
            #pragma unroll
            for (int j = 0; j < 4; j++) wv[j] = Wsm[kk][tx + 16*j];
            #pragma unroll
            for (int i = 0; i < 4; i++)
                #pragma unroll
                for (int j = 0; j < 4; j++) acc[i][j] = fmaf(hv[i], wv[j], acc[i][j]);
        }
        __syncthreads();
    }

    #pragma unroll
    for (int i = 0; i < 4; i++) {
        int r = r0 + ty + 16*i;
        #pragma unroll
        for (int j = 0; j < 4; j++) {
            int d = tx + 16*j;
            g_O[r*DD + d] = acc[i][j] + gcnB[d];
        }
    }
}

// ---------------- K5: out[b,d,n,t] = g_O[bt,n,d] ----------------
__global__ void k_out(float* __restrict__ out) {
    int b = blockIdx.x / NN, n = blockIdx.x % NN;
    __shared__ float ts[TT][DD+1];
    for (int i = threadIdx.x; i < TT*DD; i += blockDim.x) {
        int t = i / DD, d = i % DD;
        ts[t][d] = g_O[((b*TT + t)*NN + n)*DD + d];
    }
    __syncthreads();
    float* op = out + (b*DD*NN + n)*TT;
    for (int i = threadIdx.x; i < DD*TT; i += blockDim.x) {
        int d = i / TT, t = i % TT;
        op[d*NN*TT + t] = ts[t][d];
    }
}

// ---------------- launch ----------------
extern "C" void kernel_launch(void* const* d_in, const int* in_sizes, int n_in,
                              void* d_out, int out_size) {
    const float* X    = (const float*)d_in[0];
    const float* TE   = (const float*)d_in[1];
    const float* adjW = (const float*)d_in[2];
    const float* adjB = (const float*)d_in[3];
    const float* w1   = (const float*)d_in[4];
    const float* w2   = (const float*)d_in[5];
    const float* a1   = (const float*)d_in[6];
    const float* a2   = (const float*)d_in[7];
    const float* b1   = (const float*)d_in[8];
    const float* b2   = (const float*)d_in[9];
    const float* gw   = (const float*)d_in[10];
    const float* gb   = (const float*)d_in[11];
    float* out = (float*)d_out;

    k_small<<<352, 256>>>(a1, a2, b1, b2, w1, w2);
    k_packX<<<BB*NN, 128>>>(X);
    k_adj<<<dim3(BT, 5, 5), 256>>>(TE, adjW, adjB);
    for (int hop = 1; hop <= 2; hop++) {
        k_hop_agg <<<dim3(BT, 5), 256>>>((hop - 1) * DD);
        k_hop_node<<<dim3(NN, BT/64), 256>>>(hop * DD);
    }
    k_gcn<<<BT*NN/64, 256>>>(gw, gb);
    k_out<<<BB*NN, 128>>>(out);
}